// round 16
// baseline (speedup 1.0000x reference)
#include <cuda_runtime.h>
#include <math.h>

#define NPILLARS 120000
#define MPTS 32
#define CIN 9
#define COUT 63
#define WPB 8              // warps per block
#define PPW 2              // pillars per warp (small quantum -> no wave tail)
#define TOTWARPS (NPILLARS / PPW)   // 60000
#define NBLOCKS  (TOTWARPS / WPB)   // 7500
#define VX 0.16f
#define VY 0.16f
#define X_OFF (0.16f * 0.5f + 0.0f)
#define Y_OFF (0.16f * 0.5f + (-39.68f))
#define BN_EPS 1e-3f
#define FPSCALE 1048576.0f           // 2^20 fixed-point scale for centroid
#define INV_FPSCALE (1.0f / 1048576.0f)

typedef unsigned long long u64;

__device__ __forceinline__ u64 pack2(float lo, float hi) {
    u64 r;
    asm("mov.b64 %0, {%1, %2};" : "=l"(r) : "f"(lo), "f"(hi));
    return r;
}
__device__ __forceinline__ void unpack2(u64 v, float& lo, float& hi) {
    asm("mov.b64 {%0, %1}, %2;" : "=f"(lo), "=f"(hi) : "l"(v));
}
__device__ __forceinline__ u64 ffma2(u64 a, u64 b, u64 c) {
    u64 d;
    asm("fma.rn.f32x2 %0, %1, %2, %3;" : "=l"(d) : "l"(a), "l"(b), "l"(c));
    return d;
}
__device__ __forceinline__ u64 fmul2(u64 a, u64 b) {
    u64 d;
    asm("mul.rn.f32x2 %0, %1, %2;" : "=l"(d) : "l"(a), "l"(b));
    return d;
}
// integer warp reduction (sm_80+, legal on sm_103a)
__device__ __forceinline__ int redux_add_s32(int v) {
    int r;
    asm("redux.sync.add.s32 %0, %1, 0xffffffff;" : "=r"(r) : "r"(v));
    return r;
}
// 16B shared load -> two packed f32x2 (one channel of 4 consecutive points)
__device__ __forceinline__ void lds2(u64& a, u64& b, unsigned addr) {
    asm("ld.shared.v2.b64 {%0, %1}, [%2];" : "=l"(a), "=l"(b) : "r"(addr));
}

__global__ __launch_bounds__(WPB * 32, 4)
void pfn_kernel(const float* __restrict__ features,   // (N, M, 4)
                const int*   __restrict__ num_points, // (N)
                const int*   __restrict__ coors,      // (N, 4) [b, z, y, x]
                const float* __restrict__ Wmat,       // (63, 9)
                const float* __restrict__ gamma_,     // (63)
                const float* __restrict__ beta_,      // (63)
                const float* __restrict__ rmean,      // (63)
                const float* __restrict__ rvar,      // (63)
                float*       __restrict__ out)        // (N, 64)
{
    // double-buffered raw coords: pillar k uses buf (k & 1); with one pillar
    // per buffer there is no overwrite hazard at the loop tail, so only the
    // STS->LDS syncwarp remains.
    __shared__ __align__(16) float sF[WPB][2][4][MPTS];
    __shared__ float sWt[4][64];   // Wt0=W0+W4+W7, Wt1=W1+W5+W8, Wt2=W2+W6, Wt3=W3
    __shared__ float sWo[5][64];   // W'[u][4..8] for per-pillar bias fold
    __shared__ float sSh[64];      // folded BN shift (slot 63 = 0)
    __shared__ float sRnp[MPTS + 1];  // -2^-20 / np LUT

    const int tid = threadIdx.x;

    if (tid < 64) {
        float inv = 0.0f, sh = 0.0f;
        float wp[CIN];
        #pragma unroll
        for (int c = 0; c < CIN; c++) wp[c] = 0.0f;
        if (tid < COUT) {
            inv = gamma_[tid] * rsqrtf(rvar[tid] + BN_EPS);
            sh  = beta_[tid] - rmean[tid] * inv;
            #pragma unroll
            for (int c = 0; c < CIN; c++) wp[c] = Wmat[tid * CIN + c] * inv;
        }
        sSh[tid]    = sh;
        sWt[0][tid] = wp[0] + wp[4] + wp[7];
        sWt[1][tid] = wp[1] + wp[5] + wp[8];
        sWt[2][tid] = wp[2] + wp[6];
        sWt[3][tid] = wp[3];
        #pragma unroll
        for (int c = 0; c < 5; c++) sWo[c][tid] = wp[4 + c];
    } else if (tid >= 128 && tid <= 128 + MPTS) {
        const int i = tid - 128;                 // 0..32
        sRnp[i] = -INV_FPSCALE / (float)(i ? i : 1);  // correctly-rounded div
    }
    __syncthreads();

    const int w    = tid >> 5;
    const int lane = tid & 31;
    const int gw   = blockIdx.x * WPB + w;   // global warp id, 0..59999

    // ---- per-warp registers ----
    const int ul = lane, uh = lane + 32;
    float t;
    t = sWt[0][ul]; const u64 w0l = pack2(t, t);
    t = sWt[1][ul]; const u64 w1l = pack2(t, t);
    t = sWt[2][ul]; const u64 w2l = pack2(t, t);
    t = sWt[3][ul]; const u64 w3l = pack2(t, t);
    t = sWt[0][uh]; const u64 w0h = pack2(t, t);
    t = sWt[1][uh]; const u64 w1h = pack2(t, t);
    t = sWt[2][uh]; const u64 w2h = pack2(t, t);
    t = sWt[3][uh]; const u64 w3h = pack2(t, t);
    const float sh_lo = sSh[ul], sh_hi = sSh[uh];

    const unsigned fb0 = (unsigned)__cvta_generic_to_shared(&sF[w][0][0][0]);
    const float4* __restrict__ feat4 = reinterpret_cast<const float4*>(features);

    // ---- first pillar's loads ----
    int n = gw;
    float4 f4 = feat4[n * MPTS + lane];
    int np = num_points[n];
    int2 yx = *reinterpret_cast<const int2*>(coors + n * 4 + 2);  // {y, x}

    #pragma unroll 1
    for (int k = 0; k < PPW; k++) {
        // prefetch next pillar while processing this one
        float4 f4n; int npn; int2 yxn;
        if (k + 1 < PPW) {
            const int n2 = n + TOTWARPS;
            f4n = feat4[n2 * MPTS + lane];
            npn = num_points[n2];
            yxn = *reinterpret_cast<const int2*>(coors + n2 * 4 + 2);
        }

        // centroid sums via fixed-point integer warp reduction.
        // reference sums ALL 32 slots (incl. padded garbage), / np.
        const int ix = __float2int_rn(f4.x * FPSCALE);
        const int iy = __float2int_rn(f4.y * FPSCALE);
        const int iz = __float2int_rn(f4.z * FPSCALE);
        const int sxi = redux_add_s32(ix);
        const int syi = redux_add_s32(iy);
        const int szi = redux_add_s32(iz);

        // padded slots get point 0's coords -> over-read quads reproduce an
        // existing max candidate exactly (np >= 1 guaranteed)
        const float p0x = __shfl_sync(0xffffffffu, f4.x, 0);
        const float p0y = __shfl_sync(0xffffffffu, f4.y, 0);
        const float p0z = __shfl_sync(0xffffffffu, f4.z, 0);
        const float p0w = __shfl_sync(0xffffffffu, f4.w, 0);
        const bool valid = lane < np;
        const int buf = k & 1;
        sF[w][buf][0][lane] = valid ? f4.x : p0x;
        sF[w][buf][1][lane] = valid ? f4.y : p0y;
        sF[w][buf][2][lane] = valid ? f4.z : p0z;
        sF[w][buf][3][lane] = valid ? f4.w : p0w;
        __syncwarp();   // STS visible to all lanes' LDS below

        // negated means / offsets (bias consumed subtractively)
        const float nr  = sRnp[np];              // broadcast LDS, -2^-20/np
        const float nmx = (float)sxi * nr;
        const float nmy = (float)syi * nr;
        const float nmz = (float)szi * nr;
        const float nox = fmaf((float)yx.y, -VX, -X_OFF);
        const float noy = fmaf((float)yx.x, -VY, -Y_OFF);

        // b[u] = sh[u] - mx*W4 - my*W5 - mz*W6 - ox*W7 - oy*W8
        float b_lo = fmaf(nmx, sWo[0][ul], sh_lo);
        float b_hi = fmaf(nmx, sWo[0][uh], sh_hi);
        b_lo = fmaf(nmy, sWo[1][ul], b_lo);
        b_hi = fmaf(nmy, sWo[1][uh], b_hi);
        b_lo = fmaf(nmz, sWo[2][ul], b_lo);
        b_hi = fmaf(nmz, sWo[2][uh], b_hi);
        b_lo = fmaf(nox, sWo[3][ul], b_lo);
        b_hi = fmaf(nox, sWo[3][uh], b_hi);
        b_lo = fmaf(noy, sWo[4][ul], b_lo);
        b_hi = fmaf(noy, sWo[4][uh], b_hi);

        // raw max accumulators (bias added after the loop)
        float al0 = -3.4e38f, al1 = -3.4e38f, ah0 = -3.4e38f, ah1 = -3.4e38f;

        const unsigned fbase = fb0 + buf * (unsigned)(4 * MPTS * 4);
        const int nq = (np + 3) >> 2;            // quads of points
        #pragma unroll 2
        for (int j = 0; j < nq; j++) {
            const unsigned addr = fbase + j * 16;
            u64 x01, x23, y01, y23, z01, z23, q01, q23;
            lds2(x01, x23, addr);
            lds2(y01, y23, addr + 128);
            lds2(z01, z23, addr + 256);
            lds2(q01, q23, addr + 384);

            u64 v01l = fmul2(x01, w0l);
            u64 v23l = fmul2(x23, w0l);
            u64 v01h = fmul2(x01, w0h);
            u64 v23h = fmul2(x23, w0h);
            v01l = ffma2(y01, w1l, v01l);
            v23l = ffma2(y23, w1l, v23l);
            v01h = ffma2(y01, w1h, v01h);
            v23h = ffma2(y23, w1h, v23h);
            v01l = ffma2(z01, w2l, v01l);
            v23l = ffma2(z23, w2l, v23l);
            v01h = ffma2(z01, w2h, v01h);
            v23h = ffma2(z23, w2h, v23h);
            v01l = ffma2(q01, w3l, v01l);
            v23l = ffma2(q23, w3l, v23l);
            v01h = ffma2(q01, w3h, v01h);
            v23h = ffma2(q23, w3h, v23h);

            float a0, a1;
            unpack2(v01l, a0, a1); al0 = fmaxf(al0, a0); al1 = fmaxf(al1, a1);
            unpack2(v23l, a0, a1); al0 = fmaxf(al0, a0); al1 = fmaxf(al1, a1);
            unpack2(v01h, a0, a1); ah0 = fmaxf(ah0, a0); ah1 = fmaxf(ah1, a1);
            unpack2(v23h, a0, a1); ah0 = fmaxf(ah0, a0); ah1 = fmaxf(ah1, a1);
        }
        float accl = fmaxf(al0, al1) + b_lo;
        float acch = fmaxf(ah0, ah1) + b_hi;
        // padded points contribute exactly `shift` when np < 32
        if (np < MPTS) {
            accl = fmaxf(accl, sh_lo);
            acch = fmaxf(acch, sh_hi);
        }
        accl = fmaxf(accl, 0.0f);   // relu after max (monotone)
        acch = fmaxf(acch, 0.0f);

        // branch-free stores: lane 31's second slot carries num_points
        float* o = out + (size_t)n * 64;
        const float second = (lane == 31) ? (float)np : acch;
        o[lane]      = accl;        // channels 0..31
        o[32 + lane] = second;      // channels 32..62 + np at slot 63

        // no trailing syncwarp: next pillar writes the other buffer
        n += TOTWARPS;
        f4 = f4n; np = npn; yx = yxn;
    }
}

extern "C" void kernel_launch(void* const* d_in, const int* in_sizes, int n_in,
                              void* d_out, int out_size)
{
    const float* features   = (const float*)d_in[0];
    const int*   num_points = (const int*)  d_in[1];
    const int*   coors      = (const int*)  d_in[2];
    const float* Wmat       = (const float*)d_in[3];
    const float* gamma_     = (const float*)d_in[4];
    const float* beta_      = (const float*)d_in[5];
    const float* rmean      = (const float*)d_in[6];
    const float* rvar       = (const float*)d_in[7];
    float*       out        = (float*)d_out;

    pfn_kernel<<<NBLOCKS, WPB * 32>>>(features, num_points, coors, Wmat,
                                      gamma_, beta_, rmean, rvar, out);
}

// round 17
// speedup vs baseline: 1.1535x; 1.1535x over previous
#include <cuda_runtime.h>
#include <math.h>

#define NPILLARS 120000
#define MPTS 32
#define CIN 9
#define COUT 63
#define WPB 8              // warps per block
#define PPW 10             // pillars per warp
#define TOTWARPS (NPILLARS / PPW)   // 12000
#define NBLOCKS  (TOTWARPS / WPB)   // 1500
#define VX 0.16f
#define VY 0.16f
#define X_OFF (0.16f * 0.5f + 0.0f)
#define Y_OFF (0.16f * 0.5f + (-39.68f))
#define BN_EPS 1e-3f
#define FPSCALE 1048576.0f           // 2^20 fixed-point scale for centroid
#define INV_FPSCALE (1.0f / 1048576.0f)

typedef unsigned long long u64;

__device__ __forceinline__ u64 pack2(float lo, float hi) {
    u64 r;
    asm("mov.b64 %0, {%1, %2};" : "=l"(r) : "f"(lo), "f"(hi));
    return r;
}
__device__ __forceinline__ void unpack2(u64 v, float& lo, float& hi) {
    asm("mov.b64 {%0, %1}, %2;" : "=f"(lo), "=f"(hi) : "l"(v));
}
__device__ __forceinline__ u64 ffma2(u64 a, u64 b, u64 c) {
    u64 d;
    asm("fma.rn.f32x2 %0, %1, %2, %3;" : "=l"(d) : "l"(a), "l"(b), "l"(c));
    return d;
}
__device__ __forceinline__ u64 fmul2(u64 a, u64 b) {
    u64 d;
    asm("mul.rn.f32x2 %0, %1, %2;" : "=l"(d) : "l"(a), "l"(b));
    return d;
}
// integer warp reduction (sm_80+, legal on sm_103a)
__device__ __forceinline__ int redux_add_s32(int v) {
    int r;
    asm("redux.sync.add.s32 %0, %1, 0xffffffff;" : "=r"(r) : "r"(v));
    return r;
}
// 16B shared load -> two packed f32x2 (one channel of 4 consecutive points)
__device__ __forceinline__ void lds2(u64& a, u64& b, unsigned addr) {
    asm("ld.shared.v2.b64 {%0, %1}, [%2];" : "=l"(a), "=l"(b) : "r"(addr));
}

__global__ __launch_bounds__(WPB * 32, 4)
void pfn_kernel(const float* __restrict__ features,   // (N, M, 4)
                const int*   __restrict__ num_points, // (N)
                const int*   __restrict__ coors,      // (N, 4) [b, z, y, x]
                const float* __restrict__ Wmat,       // (63, 9)
                const float* __restrict__ gamma_,     // (63)
                const float* __restrict__ beta_,      // (63)
                const float* __restrict__ rmean,      // (63)
                const float* __restrict__ rvar,       // (63)
                float*       __restrict__ out)        // (N, 64)
{
    __shared__ __align__(16) float sF[WPB][4][MPTS];  // raw coords per warp
    __shared__ float sWt[4][64];   // Wt0=W0+W4+W7, Wt1=W1+W5+W8, Wt2=W2+W6, Wt3=W3
    __shared__ __align__(8) float sWo[5][64];  // W'[u][4..8] (paired LDS.64 reads)
    __shared__ __align__(8) float sSh[64];     // folded BN shift (slot 63 = 0)
    __shared__ float sRnp[MPTS + 1];           // -2^-20 / np LUT

    const int tid = threadIdx.x;

    if (tid < 64) {
        float inv = 0.0f, sh = 0.0f;
        float wp[CIN];
        #pragma unroll
        for (int c = 0; c < CIN; c++) wp[c] = 0.0f;
        if (tid < COUT) {
            inv = gamma_[tid] * rsqrtf(rvar[tid] + BN_EPS);
            sh  = beta_[tid] - rmean[tid] * inv;
            #pragma unroll
            for (int c = 0; c < CIN; c++) wp[c] = Wmat[tid * CIN + c] * inv;
        }
        sSh[tid]    = sh;
        sWt[0][tid] = wp[0] + wp[4] + wp[7];
        sWt[1][tid] = wp[1] + wp[5] + wp[8];
        sWt[2][tid] = wp[2] + wp[6];
        sWt[3][tid] = wp[3];
        #pragma unroll
        for (int c = 0; c < 5; c++) sWo[c][tid] = wp[4 + c];
    } else if (tid >= 128 && tid <= 128 + MPTS) {
        const int i = tid - 128;                 // 0..32
        sRnp[i] = -INV_FPSCALE / (float)(i ? i : 1);  // correctly-rounded div
    }
    __syncthreads();

    const int w    = tid >> 5;
    const int lane = tid & 31;
    const int gw   = blockIdx.x * WPB + w;   // global warp id, 0..11999

    // ---- per-warp registers: lane owns ADJACENT channels 2*lane, 2*lane+1 ----
    const int ul = 2 * lane, uh = 2 * lane + 1;
    float t;
    t = sWt[0][ul]; const u64 w0l = pack2(t, t);
    t = sWt[1][ul]; const u64 w1l = pack2(t, t);
    t = sWt[2][ul]; const u64 w2l = pack2(t, t);
    t = sWt[3][ul]; const u64 w3l = pack2(t, t);
    t = sWt[0][uh]; const u64 w0h = pack2(t, t);
    t = sWt[1][uh]; const u64 w1h = pack2(t, t);
    t = sWt[2][uh]; const u64 w2h = pack2(t, t);
    t = sWt[3][uh]; const u64 w3h = pack2(t, t);
    // shift pair for this lane's two channels (one 8B load, once per warp)
    const u64 shp = *reinterpret_cast<const u64*>(&sSh[ul]);
    float sh_lo, sh_hi;
    unpack2(shp, sh_lo, sh_hi);

    const unsigned fbase = (unsigned)__cvta_generic_to_shared(&sF[w][0][0]);
    const float4* __restrict__ feat4 = reinterpret_cast<const float4*>(features);

    // ---- first pillar's loads ----
    int n = gw;
    float4 f4 = feat4[n * MPTS + lane];
    int np = num_points[n];
    int2 yx = *reinterpret_cast<const int2*>(coors + n * 4 + 2);  // {y, x}

    #pragma unroll 1
    for (int k = 0; k < PPW; k++) {
        // prefetch next pillar while processing this one
        float4 f4n; int npn; int2 yxn;
        if (k + 1 < PPW) {
            const int n2 = n + TOTWARPS;
            f4n = feat4[n2 * MPTS + lane];
            npn = num_points[n2];
            yxn = *reinterpret_cast<const int2*>(coors + n2 * 4 + 2);
        }

        // centroid sums via fixed-point integer warp reduction.
        // reference sums ALL 32 slots (incl. padded garbage), / np.
        const int ix = __float2int_rn(f4.x * FPSCALE);
        const int iy = __float2int_rn(f4.y * FPSCALE);
        const int iz = __float2int_rn(f4.z * FPSCALE);
        const int sxi = redux_add_s32(ix);
        const int syi = redux_add_s32(iy);
        const int szi = redux_add_s32(iz);

        // padded slots get point 0's coords -> over-read quads reproduce an
        // existing max candidate exactly (np >= 1 guaranteed)
        const float p0x = __shfl_sync(0xffffffffu, f4.x, 0);
        const float p0y = __shfl_sync(0xffffffffu, f4.y, 0);
        const float p0z = __shfl_sync(0xffffffffu, f4.z, 0);
        const float p0w = __shfl_sync(0xffffffffu, f4.w, 0);
        const bool valid = lane < np;
        sF[w][0][lane] = valid ? f4.x : p0x;
        sF[w][1][lane] = valid ? f4.y : p0y;
        sF[w][2][lane] = valid ? f4.z : p0z;
        sF[w][3][lane] = valid ? f4.w : p0w;
        __syncwarp();   // STS visible to all lanes' LDS below

        // negated means / offsets (bias consumed subtractively)
        const float nr  = sRnp[np];              // broadcast LDS, -2^-20/np
        const float nmx = (float)sxi * nr;
        const float nmy = (float)syi * nr;
        const float nmz = (float)szi * nr;
        const float nox = fmaf((float)yx.y, -VX, -X_OFF);
        const float noy = fmaf((float)yx.x, -VY, -Y_OFF);

        // b[2l],b[2l+1] = sh - mx*W4 - my*W5 - mz*W6 - ox*W7 - oy*W8
        // adjacent channels -> packed 8B weight pairs, 5 LDS.64 + 5 FFMA2
        u64 b2 = shp;
        b2 = ffma2(pack2(nmx, nmx),
                   *reinterpret_cast<const u64*>(&sWo[0][ul]), b2);
        b2 = ffma2(pack2(nmy, nmy),
                   *reinterpret_cast<const u64*>(&sWo[1][ul]), b2);
        b2 = ffma2(pack2(nmz, nmz),
                   *reinterpret_cast<const u64*>(&sWo[2][ul]), b2);
        b2 = ffma2(pack2(nox, nox),
                   *reinterpret_cast<const u64*>(&sWo[3][ul]), b2);
        b2 = ffma2(pack2(noy, noy),
                   *reinterpret_cast<const u64*>(&sWo[4][ul]), b2);

        // raw max accumulators (bias added after the loop)
        float al0 = -3.4e38f, al1 = -3.4e38f, ah0 = -3.4e38f, ah1 = -3.4e38f;

        const int nq = (np + 3) >> 2;            // quads of points
        #pragma unroll 2
        for (int j = 0; j < nq; j++) {
            const unsigned addr = fbase + j * 16;
            u64 x01, x23, y01, y23, z01, z23, q01, q23;
            lds2(x01, x23, addr);
            lds2(y01, y23, addr + 128);
            lds2(z01, z23, addr + 256);
            lds2(q01, q23, addr + 384);

            u64 v01l = fmul2(x01, w0l);
            u64 v23l = fmul2(x23, w0l);
            u64 v01h = fmul2(x01, w0h);
            u64 v23h = fmul2(x23, w0h);
            v01l = ffma2(y01, w1l, v01l);
            v23l = ffma2(y23, w1l, v23l);
            v01h = ffma2(y01, w1h, v01h);
            v23h = ffma2(y23, w1h, v23h);
            v01l = ffma2(z01, w2l, v01l);
            v23l = ffma2(z23, w2l, v23l);
            v01h = ffma2(z01, w2h, v01h);
            v23h = ffma2(z23, w2h, v23h);
            v01l = ffma2(q01, w3l, v01l);
            v23l = ffma2(q23, w3l, v23l);
            v01h = ffma2(q01, w3h, v01h);
            v23h = ffma2(q23, w3h, v23h);

            float a0, a1;
            unpack2(v01l, a0, a1); al0 = fmaxf(al0, a0); al1 = fmaxf(al1, a1);
            unpack2(v23l, a0, a1); al0 = fmaxf(al0, a0); al1 = fmaxf(al1, a1);
            unpack2(v01h, a0, a1); ah0 = fmaxf(ah0, a0); ah1 = fmaxf(ah1, a1);
            unpack2(v23h, a0, a1); ah0 = fmaxf(ah0, a0); ah1 = fmaxf(ah1, a1);
        }
        float b_lo, b_hi;
        unpack2(b2, b_lo, b_hi);
        float accl = fmaxf(al0, al1) + b_lo;
        float acch = fmaxf(ah0, ah1) + b_hi;
        // padded points contribute exactly `shift` when np < 32
        if (np < MPTS) {
            accl = fmaxf(accl, sh_lo);
            acch = fmaxf(acch, sh_hi);
        }
        accl = fmaxf(accl, 0.0f);   // relu after max (monotone)
        acch = fmaxf(acch, 0.0f);

        // single 8B store: channels 2l, 2l+1; lane 31's hi half = channel 63 = np
        const float second = (lane == 31) ? (float)np : acch;
        float2 v2; v2.x = accl; v2.y = second;
        *reinterpret_cast<float2*>(out + (size_t)n * 64 + ul) = v2;

        __syncwarp();   // all lanes done with sF before next pillar overwrites
        n += TOTWARPS;
        f4 = f4n; np = npn; yx = yxn;
    }
}

extern "C" void kernel_launch(void* const* d_in, const int* in_sizes, int n_in,
                              void* d_out, int out_size)
{
    const float* features   = (const float*)d_in[0];
    const int*   num_points = (const int*)  d_in[1];
    const int*   coors      = (const int*)  d_in[2];
    const float* Wmat       = (const float*)d_in[3];
    const float* gamma_     = (const float*)d_in[4];
    const float* beta_      = (const float*)d_in[5];
    const float* rmean      = (const float*)d_in[6];
    const float* rvar       = (const float*)d_in[7];
    float*       out        = (float*)d_out;

    pfn_kernel<<<NBLOCKS, WPB * 32>>>(features, num_points, coors, Wmat,
                                      gamma_, beta_, rmean, rvar, out);
}